// round 2
// baseline (speedup 1.0000x reference)
#include <cuda_runtime.h>
#include <math.h>

#define HEADS   12
#define DH      64
#define SEQ     2048
#define BATCH   4
#define DMODEL  768
#define QKVW    2304      // 3 * 768
#define SCALE   0.125f    // 64^-0.5

// Scratch (device globals; no allocations allowed)
__device__ float g_qkv[(size_t)BATCH * SEQ * QKVW];    // 75.5 MB
__device__ float g_attn[(size_t)BATCH * SEQ * DMODEL]; // 25 MB

// ---------------------------------------------------------------------------
// SGEMM: C[M,N] = A[M,K] @ B[K,N] (+ bias). All row-major.
// 128x128 block tile, BK=8, 256 threads, 8x8 register tile per thread.
// Requires M%128==0, N%128==0, K%8==0 (true for all three GEMMs here).
// ---------------------------------------------------------------------------
__global__ __launch_bounds__(256)
void sgemm_bias(const float* __restrict__ A, const float* __restrict__ B,
                const float* __restrict__ bias, float* __restrict__ C,
                int M, int N, int K) {
    __shared__ float As[8][128];
    __shared__ float Bs[8][132];   // +4 pad keeps float4 alignment, avoids conflicts

    int tid = threadIdx.x;
    int tx = tid & 15, ty = tid >> 4;
    int row0 = blockIdx.y * 128, col0 = blockIdx.x * 128;

    int aRow = tid >> 1,  aCol = (tid & 1) << 2;    // A tile 128x8, float4 each
    int bRow = tid >> 5,  bCol = (tid & 31) << 2;   // B tile 8x128, float4 each

    float acc[8][8] = {};

    for (int k0 = 0; k0 < K; k0 += 8) {
        float4 a4 = *(const float4*)(A + (size_t)(row0 + aRow) * K + k0 + aCol);
        As[aCol + 0][aRow] = a4.x;
        As[aCol + 1][aRow] = a4.y;
        As[aCol + 2][aRow] = a4.z;
        As[aCol + 3][aRow] = a4.w;
        *(float4*)&Bs[bRow][bCol] =
            *(const float4*)(B + (size_t)(k0 + bRow) * N + col0 + bCol);
        __syncthreads();

        #pragma unroll
        for (int k = 0; k < 8; k++) {
            float ar[8], br[8];
            *(float4*)(ar)     = *(float4*)&As[k][ty << 3];
            *(float4*)(ar + 4) = *(float4*)&As[k][(ty << 3) + 4];
            *(float4*)(br)     = *(float4*)&Bs[k][tx << 3];
            *(float4*)(br + 4) = *(float4*)&Bs[k][(tx << 3) + 4];
            #pragma unroll
            for (int i = 0; i < 8; i++)
                #pragma unroll
                for (int j = 0; j < 8; j++)
                    acc[i][j] += ar[i] * br[j];
        }
        __syncthreads();
    }

    #pragma unroll
    for (int i = 0; i < 8; i++) {
        int row = row0 + (ty << 3) + i;
        #pragma unroll
        for (int j4 = 0; j4 < 2; j4++) {
            int col = col0 + (tx << 3) + j4 * 4;
            float4 v = make_float4(acc[i][j4*4], acc[i][j4*4+1],
                                   acc[i][j4*4+2], acc[i][j4*4+3]);
            if (bias) {
                v.x += bias[col];     v.y += bias[col + 1];
                v.z += bias[col + 2]; v.w += bias[col + 3];
            }
            *(float4*)(C + (size_t)row * N + col) = v;
        }
    }
}

// ---------------------------------------------------------------------------
// Flash attention: one block = one (batch, head, 64-row Q tile).
// Streams 64-row K/V tiles with online softmax fully in registers:
// S tile lives in a 4x4 register block per thread (16x16 thread grid);
// row max/sum reduced across the 16 tx-lanes via shfl.xor (lanes 0-15 /
// 16-31 stay within their 16-group for masks 1,2,4,8). m, l, alpha are
// replicated in registers across the 16 owners of each row.
// ---------------------------------------------------------------------------
#define QT  64
#define KT  64
#define PAD 4
#define FLASH_SMEM_FLOATS (4*QT*(DH+PAD))
#define FLASH_SMEM_BYTES  (FLASH_SMEM_FLOATS * 4)

__global__ __launch_bounds__(256)
void flash_kernel(const float* __restrict__ qkv, float* __restrict__ out) {
    extern __shared__ float sm[];
    float (*Qs)[DH + PAD] = (float(*)[DH + PAD])(sm);
    float (*Ks)[DH + PAD] = (float(*)[DH + PAD])(sm + 1 * QT * (DH + PAD));
    float (*Vs)[DH + PAD] = (float(*)[DH + PAD])(sm + 2 * QT * (DH + PAD));
    float (*Ps)[KT + PAD] = (float(*)[KT + PAD])(sm + 3 * QT * (DH + PAD));

    int b  = blockIdx.z, h = blockIdx.y;
    int q0 = blockIdx.x * QT;
    int tid = threadIdx.x;
    int tx = tid & 15, ty = tid >> 4;

    const float* base = qkv + (size_t)b * SEQ * QKVW;
    int hc = h * DH;   // head column offset within q / k / v slabs

    // Load Q tile [64][64]
    #pragma unroll
    for (int i = 0; i < 4; i++) {
        int idx = tid + i * 256;
        int r = idx >> 4, c = (idx & 15) << 2;
        *(float4*)&Qs[r][c] =
            *(const float4*)(base + (size_t)(q0 + r) * QKVW + hc + c);
    }

    float o[4][4] = {};
    float m_i[4], l_i[4];
    #pragma unroll
    for (int i = 0; i < 4; i++) { m_i[i] = -INFINITY; l_i[i] = 0.f; }
    __syncthreads();

    for (int kt = 0; kt < SEQ / KT; kt++) {
        int k0 = kt * KT;
        // Load K and V tiles
        #pragma unroll
        for (int i = 0; i < 4; i++) {
            int idx = tid + i * 256;
            int r = idx >> 4, c = (idx & 15) << 2;
            const float* src = base + (size_t)(k0 + r) * QKVW;
            *(float4*)&Ks[r][c] = *(const float4*)(src + DMODEL     + hc + c);
            *(float4*)&Vs[r][c] = *(const float4*)(src + 2 * DMODEL + hc + c);
        }
        __syncthreads();

        // S = (Q @ K^T) * SCALE : 4x4 per thread, float4 over d
        float s[4][4] = {};
        #pragma unroll
        for (int d4 = 0; d4 < DH / 4; d4++) {
            float4 q4[4], k4[4];
            #pragma unroll
            for (int i = 0; i < 4; i++) q4[i] = *(float4*)&Qs[(ty << 2) + i][d4 << 2];
            #pragma unroll
            for (int j = 0; j < 4; j++) k4[j] = *(float4*)&Ks[(tx << 2) + j][d4 << 2];
            #pragma unroll
            for (int i = 0; i < 4; i++)
                #pragma unroll
                for (int j = 0; j < 4; j++)
                    s[i][j] += q4[i].x * k4[j].x + q4[i].y * k4[j].y
                             + q4[i].z * k4[j].z + q4[i].w * k4[j].w;
        }

        // Online softmax in registers; reduce across the 16 tx-lanes.
        float alpha[4];
        #pragma unroll
        for (int i = 0; i < 4; i++) {
            float tm = fmaxf(fmaxf(s[i][0], s[i][1]), fmaxf(s[i][2], s[i][3]));
            tm *= SCALE;   // fold scale into stats; scale s below
            #pragma unroll
            for (int w = 1; w < 16; w <<= 1)
                tm = fmaxf(tm, __shfl_xor_sync(0xffffffffu, tm, w));
            float mnew = fmaxf(m_i[i], tm);
            alpha[i] = __expf(m_i[i] - mnew);   // first tile: exp(-inf)=0
            m_i[i] = mnew;

            float sum = 0.f;
            #pragma unroll
            for (int j = 0; j < 4; j++) {
                float p = __expf(s[i][j] * SCALE - mnew);
                s[i][j] = p;
                sum += p;
            }
            #pragma unroll
            for (int w = 1; w < 16; w <<= 1)
                sum += __shfl_xor_sync(0xffffffffu, sum, w);
            l_i[i] = l_i[i] * alpha[i] + sum;
        }

        // Stage P into smem for the PV matmul
        #pragma unroll
        for (int i = 0; i < 4; i++)
            *(float4*)&Ps[(ty << 2) + i][tx << 2] =
                make_float4(s[i][0], s[i][1], s[i][2], s[i][3]);
        __syncthreads();

        // O = O * alpha + P @ V
        #pragma unroll
        for (int i = 0; i < 4; i++) {
            float a = alpha[i];
            #pragma unroll
            for (int j = 0; j < 4; j++) o[i][j] *= a;
        }
        #pragma unroll
        for (int m4 = 0; m4 < KT / 4; m4++) {
            float4 p4[4], v4[4];
            #pragma unroll
            for (int i = 0; i < 4; i++)  p4[i]  = *(float4*)&Ps[(ty << 2) + i][m4 << 2];
            #pragma unroll
            for (int mm = 0; mm < 4; mm++) v4[mm] = *(float4*)&Vs[(m4 << 2) + mm][tx << 2];
            #pragma unroll
            for (int i = 0; i < 4; i++) {
                float pi[4] = { p4[i].x, p4[i].y, p4[i].z, p4[i].w };
                #pragma unroll
                for (int mm = 0; mm < 4; mm++) {
                    o[i][0] += pi[mm] * v4[mm].x;
                    o[i][1] += pi[mm] * v4[mm].y;
                    o[i][2] += pi[mm] * v4[mm].z;
                    o[i][3] += pi[mm] * v4[mm].w;
                }
            }
        }
        __syncthreads();   // protect Ks/Vs/Ps before next tile
    }

    // Normalize and write out in 'b n (h d)' layout
    #pragma unroll
    for (int i = 0; i < 4; i++) {
        int r = (ty << 2) + i;
        float inv = 1.f / l_i[i];
        float4 v = make_float4(o[i][0] * inv, o[i][1] * inv,
                               o[i][2] * inv, o[i][3] * inv);
        *(float4*)(out + (size_t)((size_t)b * SEQ + q0 + r) * DMODEL + hc + (tx << 2)) = v;
    }
}

// ---------------------------------------------------------------------------
extern "C" void kernel_launch(void* const* d_in, const int* in_sizes, int n_in,
                              void* d_out, int out_size) {
    const float* x     = (const float*)d_in[0];   // [4,2048,768]
    const float* W_qkv = (const float*)d_in[1];   // [768,2304]
    const float* W_out = (const float*)d_in[2];   // [768,768]
    const float* b_out = (const float*)d_in[3];   // [768]
    float* out = (float*)d_out;                   // [4,2048,768]

    float* qkv;  cudaGetSymbolAddress((void**)&qkv,  g_qkv);
    float* attn; cudaGetSymbolAddress((void**)&attn, g_attn);

    cudaFuncSetAttribute(flash_kernel,
                         cudaFuncAttributeMaxDynamicSharedMemorySize,
                         FLASH_SMEM_BYTES);

    const int M = BATCH * SEQ;  // 8192

    // 1) qkv = x @ W_qkv
    sgemm_bias<<<dim3(QKVW / 128, M / 128), 256>>>(
        x, W_qkv, nullptr, qkv, M, QKVW, DMODEL);

    // 2) attention per (b, h, q-tile)
    flash_kernel<<<dim3(SEQ / QT, HEADS, BATCH), 256, FLASH_SMEM_BYTES>>>(
        qkv, attn);

    // 3) out = attn @ W_out + b_out
    sgemm_bias<<<dim3(DMODEL / 128, M / 128), 256>>>(
        attn, W_out, b_out, out, M, DMODEL, DMODEL);
}

// round 3
// speedup vs baseline: 3.8094x; 3.8094x over previous
#include <cuda_runtime.h>
#include <math.h>
#include <stdint.h>

#define HEADS   12
#define DH      64
#define SEQ     2048
#define BATCH   4
#define DMODEL  768
#define QKVW    2304      // 3 * 768
#define SCALE   0.125f    // 64^-0.5

// Scratch (device globals; no allocations allowed)
__device__ float g_qkv[(size_t)BATCH * SEQ * QKVW];    // 75.5 MB
__device__ float g_attn[(size_t)BATCH * SEQ * DMODEL]; // 25 MB

// ---------------------------------------------------------------------------
// tf32 helpers
// ---------------------------------------------------------------------------
__device__ __forceinline__ uint32_t f2tf32(float f) {
    uint32_t u;
    asm("cvt.rna.tf32.f32 %0, %1;" : "=r"(u) : "f"(f));
    return u;
}

// D = A(16x8) @ B(8x8) + D, tf32 inputs, fp32 accum.
__device__ __forceinline__ void mma_tf32(float c[4],
                                         uint32_t a0, uint32_t a1,
                                         uint32_t a2, uint32_t a3,
                                         uint32_t b0, uint32_t b1) {
    asm volatile(
        "mma.sync.aligned.m16n8k8.row.col.f32.tf32.tf32.f32 "
        "{%0,%1,%2,%3}, {%4,%5,%6,%7}, {%8,%9}, {%0,%1,%2,%3};\n"
        : "+f"(c[0]), "+f"(c[1]), "+f"(c[2]), "+f"(c[3])
        : "r"(a0), "r"(a1), "r"(a2), "r"(a3), "r"(b0), "r"(b1));
}

// ---------------------------------------------------------------------------
// GEMM (tf32 tensor cores): C[M,N] = A[M,K] @ B[K,N] (+ bias), row-major.
// 128x128 block tile, BK=32, 256 threads = 8 warps (2x4), warp tile 64x32.
// Global loads are software-pipelined (prefetch regs), tf32 cvt on smem store.
// ---------------------------------------------------------------------------
#define BM 128
#define BN 128
#define BK 32

__global__ __launch_bounds__(256)
void gemm_tf32(const float* __restrict__ A, const float* __restrict__ B,
               const float* __restrict__ bias, float* __restrict__ C,
               int M, int N, int K) {
    __shared__ uint32_t As[BM][BK + 4];   // stride 36: frag loads conflict-free
    __shared__ uint32_t Bs[BK][BN + 4];   // stride 132

    int tid  = threadIdx.x;
    int lane = tid & 31, wid = tid >> 5;
    int wm = (wid >> 2) * 64;    // warp m offset in tile (0|64)
    int wn = (wid & 3) * 32;     // warp n offset in tile (0..96)
    int g  = lane >> 2, q = lane & 3;   // fragment group / in-group id

    int row0 = blockIdx.y * BM, col0 = blockIdx.x * BN;

    int aRow = tid >> 3,       aCol = (tid & 7) << 2;    // A: 128x32, 4 f4/thr
    int bRow = tid >> 5,       bCol = (tid & 31) << 2;   // B: 32x128, 4 f4/thr

    float acc[4][4][4] = {};   // [mt][nt][reg]
    float4 pa[4], pb[4];

    #pragma unroll
    for (int i = 0; i < 4; i++)
        pa[i] = *(const float4*)(A + (size_t)(row0 + aRow + 32 * i) * K + aCol);
    #pragma unroll
    for (int i = 0; i < 4; i++)
        pb[i] = *(const float4*)(B + (size_t)(bRow + 8 * i) * N + col0 + bCol);

    for (int k0 = 0; k0 < K; k0 += BK) {
        // stage prefetched tile into smem as tf32
        #pragma unroll
        for (int i = 0; i < 4; i++) {
            uint4 u = make_uint4(f2tf32(pa[i].x), f2tf32(pa[i].y),
                                 f2tf32(pa[i].z), f2tf32(pa[i].w));
            *(uint4*)&As[aRow + 32 * i][aCol] = u;
        }
        #pragma unroll
        for (int i = 0; i < 4; i++) {
            uint4 u = make_uint4(f2tf32(pb[i].x), f2tf32(pb[i].y),
                                 f2tf32(pb[i].z), f2tf32(pb[i].w));
            *(uint4*)&Bs[bRow + 8 * i][bCol] = u;
        }
        __syncthreads();

        int kn = k0 + BK;
        if (kn < K) {
            #pragma unroll
            for (int i = 0; i < 4; i++)
                pa[i] = *(const float4*)(A + (size_t)(row0 + aRow + 32 * i) * K + kn + aCol);
            #pragma unroll
            for (int i = 0; i < 4; i++)
                pb[i] = *(const float4*)(B + (size_t)(kn + bRow + 8 * i) * N + col0 + bCol);
        }

        #pragma unroll
        for (int ks = 0; ks < BK / 8; ks++) {
            int kk = ks * 8;
            uint32_t af[4][4];
            #pragma unroll
            for (int mt = 0; mt < 4; mt++) {
                int r = wm + mt * 16;
                af[mt][0] = As[r + g    ][kk + q    ];
                af[mt][1] = As[r + g + 8][kk + q    ];
                af[mt][2] = As[r + g    ][kk + q + 4];
                af[mt][3] = As[r + g + 8][kk + q + 4];
            }
            uint32_t bf[4][2];
            #pragma unroll
            for (int nt = 0; nt < 4; nt++) {
                int c = wn + nt * 8 + g;
                bf[nt][0] = Bs[kk + q    ][c];
                bf[nt][1] = Bs[kk + q + 4][c];
            }
            #pragma unroll
            for (int mt = 0; mt < 4; mt++)
                #pragma unroll
                for (int nt = 0; nt < 4; nt++)
                    mma_tf32(acc[mt][nt], af[mt][0], af[mt][1], af[mt][2], af[mt][3],
                             bf[nt][0], bf[nt][1]);
        }
        __syncthreads();
    }

    // epilogue
    #pragma unroll
    for (int mt = 0; mt < 4; mt++) {
        int r = row0 + wm + mt * 16 + g;
        #pragma unroll
        for (int nt = 0; nt < 4; nt++) {
            int c = col0 + wn + nt * 8 + 2 * q;
            float bx = 0.f, by = 0.f;
            if (bias) { bx = bias[c]; by = bias[c + 1]; }
            *(float2*)(C + (size_t)r * N + c) =
                make_float2(acc[mt][nt][0] + bx, acc[mt][nt][1] + by);
            *(float2*)(C + (size_t)(r + 8) * N + c) =
                make_float2(acc[mt][nt][2] + bx, acc[mt][nt][3] + by);
        }
    }
}

// ---------------------------------------------------------------------------
// Flash attention (tf32 tensor cores): block = (b, h, 64-row Q tile),
// 128 threads = 4 warps, each warp owns a 16-row strip. Online softmax on
// C-fragments with quad-lane shfl reductions; P staged via warp-private smem.
// ---------------------------------------------------------------------------
#define FDH 68   // 64 + 4 pad
#define FLASH_SMEM_BYTES (4 * 64 * FDH * 4)

__global__ __launch_bounds__(128)
void flash_tf32(const float* __restrict__ qkv, float* __restrict__ out) {
    extern __shared__ float sm[];
    float* Qs = sm;                 // [64][68] tf32 bits (Q * SCALE)
    float* Ks = sm + 64 * FDH;
    float* Vs = sm + 2 * 64 * FDH;
    float* Ps = sm + 3 * 64 * FDH;

    int b  = blockIdx.z, h = blockIdx.y;
    int q0 = blockIdx.x * 64;
    int tid = threadIdx.x;
    int lane = tid & 31, wid = tid >> 5;
    int g = lane >> 2, qd = lane & 3;
    int m0 = wid * 16;

    const float* base = qkv + (size_t)b * SEQ * QKVW;
    int hc = h * DH;

    // Q tile [64][64], pre-scaled by 2^-3 (exact), tf32-rounded
    #pragma unroll
    for (int i = 0; i < 8; i++) {
        int f = tid + i * 128;
        int r = f >> 4, c = (f & 15) << 2;
        float4 v = *(const float4*)(base + (size_t)(q0 + r) * QKVW + hc + c);
        uint4 u = make_uint4(f2tf32(v.x * SCALE), f2tf32(v.y * SCALE),
                             f2tf32(v.z * SCALE), f2tf32(v.w * SCALE));
        *(uint4*)&Qs[r * FDH + c] = u;
    }

    float o[8][4] = {};
    float mr0 = -INFINITY, mr1 = -INFINITY, l0 = 0.f, l1 = 0.f;
    __syncthreads();

    for (int kt = 0; kt < SEQ / 64; kt++) {
        int k0 = kt * 64;
        #pragma unroll
        for (int i = 0; i < 8; i++) {
            int f = tid + i * 128;
            int r = f >> 4, c = (f & 15) << 2;
            const float* src = base + (size_t)(k0 + r) * QKVW + hc + c;
            float4 kv = *(const float4*)(src + DMODEL);
            float4 vv = *(const float4*)(src + 2 * DMODEL);
            *(uint4*)&Ks[r * FDH + c] =
                make_uint4(f2tf32(kv.x), f2tf32(kv.y), f2tf32(kv.z), f2tf32(kv.w));
            *(uint4*)&Vs[r * FDH + c] =
                make_uint4(f2tf32(vv.x), f2tf32(vv.y), f2tf32(vv.z), f2tf32(vv.w));
        }
        __syncthreads();

        // S(16x64) = Qstrip @ K^T   (scale already folded into Q)
        float s[8][4] = {};
        #pragma unroll
        for (int ks = 0; ks < 8; ks++) {
            int kk = ks * 8;
            uint32_t a0 = __float_as_uint(Qs[(m0 + g    ) * FDH + kk + qd    ]);
            uint32_t a1 = __float_as_uint(Qs[(m0 + g + 8) * FDH + kk + qd    ]);
            uint32_t a2 = __float_as_uint(Qs[(m0 + g    ) * FDH + kk + qd + 4]);
            uint32_t a3 = __float_as_uint(Qs[(m0 + g + 8) * FDH + kk + qd + 4]);
            #pragma unroll
            for (int nt = 0; nt < 8; nt++) {
                uint32_t b0 = __float_as_uint(Ks[(nt * 8 + g) * FDH + kk + qd    ]);
                uint32_t b1 = __float_as_uint(Ks[(nt * 8 + g) * FDH + kk + qd + 4]);
                mma_tf32(s[nt], a0, a1, a2, a3, b0, b1);
            }
        }

        // online softmax: rows (m0+g) and (m0+g+8); 4 lanes per row
        float mx0 = -INFINITY, mx1 = -INFINITY;
        #pragma unroll
        for (int nt = 0; nt < 8; nt++) {
            mx0 = fmaxf(mx0, fmaxf(s[nt][0], s[nt][1]));
            mx1 = fmaxf(mx1, fmaxf(s[nt][2], s[nt][3]));
        }
        #pragma unroll
        for (int w = 1; w < 4; w <<= 1) {
            mx0 = fmaxf(mx0, __shfl_xor_sync(0xffffffffu, mx0, w));
            mx1 = fmaxf(mx1, __shfl_xor_sync(0xffffffffu, mx1, w));
        }
        float mn0 = fmaxf(mr0, mx0), mn1 = fmaxf(mr1, mx1);
        float al0 = __expf(mr0 - mn0), al1 = __expf(mr1 - mn1);
        mr0 = mn0; mr1 = mn1;

        float sum0 = 0.f, sum1 = 0.f;
        #pragma unroll
        for (int nt = 0; nt < 8; nt++) {
            s[nt][0] = __expf(s[nt][0] - mn0); sum0 += s[nt][0];
            s[nt][1] = __expf(s[nt][1] - mn0); sum0 += s[nt][1];
            s[nt][2] = __expf(s[nt][2] - mn1); sum1 += s[nt][2];
            s[nt][3] = __expf(s[nt][3] - mn1); sum1 += s[nt][3];
        }
        #pragma unroll
        for (int w = 1; w < 4; w <<= 1) {
            sum0 += __shfl_xor_sync(0xffffffffu, sum0, w);
            sum1 += __shfl_xor_sync(0xffffffffu, sum1, w);
        }
        l0 = l0 * al0 + sum0;
        l1 = l1 * al1 + sum1;

        // stage P (C-frag layout -> smem, tf32); warp-private rows
        #pragma unroll
        for (int nt = 0; nt < 8; nt++) {
            int c = nt * 8 + 2 * qd;
            Ps[(m0 + g    ) * FDH + c    ] = __uint_as_float(f2tf32(s[nt][0]));
            Ps[(m0 + g    ) * FDH + c + 1] = __uint_as_float(f2tf32(s[nt][1]));
            Ps[(m0 + g + 8) * FDH + c    ] = __uint_as_float(f2tf32(s[nt][2]));
            Ps[(m0 + g + 8) * FDH + c + 1] = __uint_as_float(f2tf32(s[nt][3]));
        }
        __syncwarp();

        // O = O*alpha + P @ V
        #pragma unroll
        for (int nt = 0; nt < 8; nt++) {
            o[nt][0] *= al0; o[nt][1] *= al0;
            o[nt][2] *= al1; o[nt][3] *= al1;
        }
        #pragma unroll
        for (int ks = 0; ks < 8; ks++) {
            int kk = ks * 8;
            uint32_t a0 = __float_as_uint(Ps[(m0 + g    ) * FDH + kk + qd    ]);
            uint32_t a1 = __float_as_uint(Ps[(m0 + g + 8) * FDH + kk + qd    ]);
            uint32_t a2 = __float_as_uint(Ps[(m0 + g    ) * FDH + kk + qd + 4]);
            uint32_t a3 = __float_as_uint(Ps[(m0 + g + 8) * FDH + kk + qd + 4]);
            #pragma unroll
            for (int nt = 0; nt < 8; nt++) {
                uint32_t b0 = __float_as_uint(Vs[(kk + qd    ) * FDH + nt * 8 + g]);
                uint32_t b1 = __float_as_uint(Vs[(kk + qd + 4) * FDH + nt * 8 + g]);
                mma_tf32(o[nt], a0, a1, a2, a3, b0, b1);
            }
        }
        __syncthreads();   // Ks/Vs fully consumed before next tile's stores
    }

    // normalize + write 'b n (h d)'
    float inv0 = 1.f / l0, inv1 = 1.f / l1;
    #pragma unroll
    for (int nt = 0; nt < 8; nt++) {
        int r = q0 + m0 + g;
        int c = hc + nt * 8 + 2 * qd;
        *(float2*)(out + (size_t)((size_t)b * SEQ + r) * DMODEL + c) =
            make_float2(o[nt][0] * inv0, o[nt][1] * inv0);
        *(float2*)(out + (size_t)((size_t)b * SEQ + r + 8) * DMODEL + c) =
            make_float2(o[nt][2] * inv1, o[nt][3] * inv1);
    }
}

// ---------------------------------------------------------------------------
extern "C" void kernel_launch(void* const* d_in, const int* in_sizes, int n_in,
                              void* d_out, int out_size) {
    const float* x     = (const float*)d_in[0];   // [4,2048,768]
    const float* W_qkv = (const float*)d_in[1];   // [768,2304]
    const float* W_out = (const float*)d_in[2];   // [768,768]
    const float* b_out = (const float*)d_in[3];   // [768]
    float* out = (float*)d_out;                   // [4,2048,768]

    float* qkv;  cudaGetSymbolAddress((void**)&qkv,  g_qkv);
    float* attn; cudaGetSymbolAddress((void**)&attn, g_attn);

    cudaFuncSetAttribute(flash_tf32,
                         cudaFuncAttributeMaxDynamicSharedMemorySize,
                         FLASH_SMEM_BYTES);

    const int M = BATCH * SEQ;  // 8192

    // 1) qkv = x @ W_qkv
    gemm_tf32<<<dim3(QKVW / BN, M / BM), 256>>>(
        x, W_qkv, nullptr, qkv, M, QKVW, DMODEL);

    // 2) attention per (b, h, q-tile)
    flash_tf32<<<dim3(SEQ / 64, HEADS, BATCH), 128, FLASH_SMEM_BYTES>>>(
        qkv, attn);

    // 3) out = attn @ W_out + b_out
    gemm_tf32<<<dim3(DMODEL / BN, M / BM), 256>>>(
        attn, W_out, b_out, out, M, DMODEL, DMODEL);
}